// round 16
// baseline (speedup 1.0000x reference)
#include <cuda_runtime.h>
#include <cuda_fp16.h>
#include <cstdint>

#define NROWS  300000
#define HD     128
#define NLANES 25000
#define LNEPS  1e-5f
#define TM64   64
#define NT64   ((NROWS + TM64 - 1) / TM64)  // 4688 tiles (64-row)
#define NLT    ((NLANES + 127) / 128)       // 196 lane tiles
#define PADU   68                            // u32 per 128-fp16 row (272B, conflict-free)
#define ROWB   272
#define TU64H  1088                          // uint4 per 64-row fp16 tile image

typedef unsigned int       u32;
typedef unsigned short     u16;
typedef unsigned long long u64;

// ---------------- device scratch ----------------
__device__ uint4 g_h[(size_t)NT64 * TU64H];  // fc1 output image (fp16, 64-row tiles)
__device__ int   g_lanemax[NLANES * HD];     // per-lane max (float bits, relu>=0)
__device__ float g_z[(size_t)NLANES * HD];   // per-lane Z = max @ w2a_bot + b2a

// ---------------- helpers ----------------
static __device__ __forceinline__ u32 smem_u32(const void* p) {
    u32 a;
    asm("{ .reg .u64 t; cvta.to.shared.u64 t, %1; cvt.u32.u64 %0, t; }" : "=r"(a) : "l"(p));
    return a;
}
static __device__ __forceinline__ u32 pack_f16(float v0, float v1) {
    __half2 h = __floats2half2_rn(v0, v1);
    return *reinterpret_cast<u32*>(&h);
}

#define CP16(sm_addr, gptr) \
    asm volatile("cp.async.cg.shared.global [%0], [%1], 16;" :: "r"(sm_addr), "l"(gptr))
#define CP_COMMIT() asm volatile("cp.async.commit_group;" ::: "memory")
#define CP_WAIT0()  asm volatile("cp.async.wait_group 0;" ::: "memory")
#define PREF_L2(p)  asm volatile("prefetch.global.L2 [%0];" :: "l"(p))

static __device__ __forceinline__ void ldsm4(u32& r0, u32& r1, u32& r2, u32& r3, u32 addr) {
    asm volatile("ldmatrix.sync.aligned.m8n8.x4.shared.b16 {%0,%1,%2,%3}, [%4];"
        : "=r"(r0), "=r"(r1), "=r"(r2), "=r"(r3) : "r"(addr));
}
static __device__ __forceinline__ void mma_f16(float (&d)[4], const u32 (&a)[4], u32 b0, u32 b1) {
    asm volatile("mma.sync.aligned.m16n8k16.row.col.f32.f16.f16.f32 "
        "{%0,%1,%2,%3}, {%4,%5,%6,%7}, {%8,%9}, {%0,%1,%2,%3};"
        : "+f"(d[0]), "+f"(d[1]), "+f"(d[2]), "+f"(d[3])
        : "r"(a[0]), "r"(a[1]), "r"(a[2]), "r"(a[3]), "r"(b0), "r"(b1));
}

// fp16 1-pass GEMM, warp tile 16x32: acc[nt 0..3] over K=128.
static __device__ __forceinline__ void gemm16x32(
    u32 A, u32 B, u32 aoff, u32 boff, float (&acc)[4][4])
{
    #pragma unroll
    for (int kc = 0; kc < 8; ++kc) {
        const u32 ka = kc * 32;
        u32 a[4], b0[4], b1[4];
        ldsm4(a[0], a[1], a[2], a[3], A + aoff + ka);
        ldsm4(b0[0], b0[1], b0[2], b0[3], B + boff + ka);
        ldsm4(b1[0], b1[1], b1[2], b1[3], B + boff + 16 * ROWB + ka);
        mma_f16(acc[0], a, b0[0], b0[1]);
        mma_f16(acc[1], a, b0[2], b0[3]);
        mma_f16(acc[2], a, b1[0], b1[1]);
        mma_f16(acc[3], a, b1[2], b1[3]);
    }
}

// ---------------- LN epilogue (16-row warp tile; single barrier; ping-pong RS/RQ) ----------------
// 16 warps: rg = w&3 (16-row group), cg = w>>2 (32-col group). RS/RQ: [4][64].
template<bool HASB, bool RELU>
static __device__ __forceinline__ void ln16(
    float (&acc)[4][4], int wrow, int wcol, int lr, int lc, int cg,
    const float* __restrict__ bias, const float* __restrict__ gam,
    const float* __restrict__ bet, float* RS, float* RQ)
{
    float s[2] = {0.f, 0.f}, q[2] = {0.f, 0.f};
    #pragma unroll
    for (int nt = 0; nt < 4; ++nt) {
        float* a = acc[nt];
        if (HASB) {
            int c = wcol + nt * 8 + lc * 2;
            float bx = bias[c], by = bias[c + 1];
            a[0] += bx; a[1] += by; a[2] += bx; a[3] += by;
        }
        s[0] += a[0] + a[1]; q[0] += a[0]*a[0] + a[1]*a[1];
        s[1] += a[2] + a[3]; q[1] += a[2]*a[2] + a[3]*a[3];
    }
    #pragma unroll
    for (int off = 1; off <= 2; off <<= 1) {
        s[0] += __shfl_xor_sync(0xffffffffu, s[0], off);
        s[1] += __shfl_xor_sync(0xffffffffu, s[1], off);
        q[0] += __shfl_xor_sync(0xffffffffu, q[0], off);
        q[1] += __shfl_xor_sync(0xffffffffu, q[1], off);
    }
    if (lc == 0) {
        RS[cg * 64 + wrow + lr]     = s[0];
        RS[cg * 64 + wrow + 8 + lr] = s[1];
        RQ[cg * 64 + wrow + lr]     = q[0];
        RQ[cg * 64 + wrow + 8 + lr] = q[1];
    }
    __syncthreads();
    float mm[2], rsd[2];
    #pragma unroll
    for (int i = 0; i < 2; ++i) {
        int row = wrow + i * 8 + lr;
        float S = RS[row] + RS[64 + row] + RS[128 + row] + RS[192 + row];
        float Q = RQ[row] + RQ[64 + row] + RQ[128 + row] + RQ[192 + row];
        float m = S * (1.f / 128.f);
        mm[i] = m;
        rsd[i] = rsqrtf(Q * (1.f / 128.f) - m * m + LNEPS);
    }
    #pragma unroll
    for (int nt = 0; nt < 4; ++nt) {
        int c = wcol + nt * 8 + lc * 2;
        float gx = gam[c], gy = gam[c + 1], ex = bet[c], ey = bet[c + 1];
        float* a = acc[nt];
        a[0] = (a[0] - mm[0]) * rsd[0] * gx + ex;
        a[1] = (a[1] - mm[0]) * rsd[0] * gy + ey;
        a[2] = (a[2] - mm[1]) * rsd[1] * gx + ex;
        a[3] = (a[3] - mm[1]) * rsd[1] * gy + ey;
        if (RELU) {
            a[0] = fmaxf(a[0], 0.f); a[1] = fmaxf(a[1], 0.f);
            a[2] = fmaxf(a[2], 0.f); a[3] = fmaxf(a[3], 0.f);
        }
    }
}

// fp16 fragment store (16-row warp tile)
static __device__ __forceinline__ void store_acc16(
    const float (&acc)[4][4], u32* dst, int wrow, int wcol, int lr, int lc)
{
    #pragma unroll
    for (int hh = 0; hh < 2; ++hh) {
        int row = wrow + hh * 8 + lr;
        u32 base = row * PADU + (wcol >> 1) + lc;
        #pragma unroll
        for (int nt = 0; nt < 4; ++nt)
            dst[base + nt*4] = pack_f16(acc[nt][hh*2+0], acc[nt][hh*2+1]);
    }
}

static __device__ __forceinline__ void store4_f16(u32* dst, int row, int col, float4 xv) {
    u32 idx = row * PADU + (col >> 1);
    dst[idx]   = pack_f16(xv.x, xv.y);
    dst[idx+1] = pack_f16(xv.z, xv.w);
}

static __device__ __forceinline__ void load_w_f16(u32* dst, const float* __restrict__ w,
                                                  int tid, int nth) {
    for (int idx = tid; idx < HD * HD / 2; idx += nth) {
        int o = idx & 127, k2 = idx >> 7;
        dst[o * PADU + k2] = pack_f16(w[(2*k2) * HD + o], w[(2*k2+1) * HD + o]);
    }
}

__global__ void k_init_lanemax() {
    int i = blockIdx.x * blockDim.x + threadIdx.x;
    if (i < NLANES * HD) g_lanemax[i] = 0;
}

#define WSZ  34816    // 128x68 u32
#define ASZ  17408    // 64x68 u32

static __device__ __forceinline__ u32 mk_aoff(int wrow, int lane) {
    return (u32)((wrow + (lane & 15)) * ROWB + ((lane >> 4) & 1) * 16);
}
static __device__ __forceinline__ u32 mk_boff(int wcol, int lane) {
    return (u32)((wcol + ((lane >> 4) & 1) * 8 + (lane & 7)) * ROWB + ((lane >> 3) & 1) * 16);
}

// ======================== fc1 (fp16 1-pass, 64-row tile, 16 warps, 2 CTAs/SM) ========================
// smem: WA 0 | WB WSZ | A 2WSZ | P 2WSZ+ASZ (3072B) | RS/RQ x2 (4x1024)
__global__ void __launch_bounds__(512, 2) k_fc1(
    const float* __restrict__ x, const int* __restrict__ lane_ids,
    const float* __restrict__ w1a, const float* __restrict__ b1a,
    const float* __restrict__ g1a, const float* __restrict__ be1a,
    const float* __restrict__ w1b, const float* __restrict__ b1b,
    const float* __restrict__ g1b, const float* __restrict__ be1b)
{
    extern __shared__ char sm[];
    u32* WA = (u32*)(sm);
    u32* WB = (u32*)(sm + WSZ);
    u32* A  = (u32*)(sm + 2*WSZ);
    float* P   = (float*)(sm + 2*WSZ + ASZ);
    float* RS0 = (float*)(sm + 2*WSZ + ASZ + 3072);
    float* RQ0 = (float*)(sm + 2*WSZ + ASZ + 4096);
    float* RS1 = (float*)(sm + 2*WSZ + ASZ + 5120);
    float* RQ1 = (float*)(sm + 2*WSZ + ASZ + 6144);

    const int tid = threadIdx.x, w = tid >> 5, lane = tid & 31;
    const int lr = lane >> 2, lc = lane & 3;
    const int wrow = (w & 3) * 16, wcol = (w >> 2) * 32, cg = w >> 2;
    const u32 aoff = mk_aoff(wrow, lane), boff = mk_boff(wcol, lane);
    const u32 sA = smem_u32(A), sWA = smem_u32(WA), sWB = smem_u32(WB);

    load_w_f16(WA, w1a, tid, 512);
    load_w_f16(WB, w1b, tid, 512);
    for (int i = tid; i < HD; i += 512) {
        P[i] = b1a[i]; P[128+i] = g1a[i]; P[256+i] = be1a[i];
        P[384+i] = b1b[i]; P[512+i] = g1b[i]; P[640+i] = be1b[i];
    }
    if (tid < 256) {
        int grow = blockIdx.x * TM64 + (tid >> 2);
        if (grow < NROWS) PREF_L2((const char*)x + (size_t)blockIdx.x * TM64 * HD * 4 + tid * 128);
    }
    __syncthreads();

    for (int t = blockIdx.x; t < NT64; t += gridDim.x) {
        int r0 = t * TM64;
        // load + convert x tile (2048 float4)
        #pragma unroll
        for (int j = 0; j < 4; ++j) {
            int idx = tid + j * 512; int xr = idx >> 5; int cgp = idx & 31;
            int grow = r0 + xr; if (grow >= NROWS) grow = NROWS - 1;
            float4 xv = __ldg(((const float4*)x) + ((size_t)grow * 32 + cgp));
            store4_f16(A, xr, cgp * 4, xv);
        }
        {
            int tn = t + gridDim.x; if (tn >= NT64) tn = t;
            if (tid < 256) {
                int grow = tn * TM64 + (tid >> 2);
                if (grow < NROWS) PREF_L2((const char*)x + (size_t)tn * TM64 * HD * 4 + tid * 128);
            }
        }
        __syncthreads();

        float acc[4][4];
        #pragma unroll
        for (int i = 0; i < 4; ++i) { acc[i][0]=acc[i][1]=acc[i][2]=acc[i][3]=0.f; }
        gemm16x32(sA, sWA, aoff, boff, acc);
        ln16<true, true>(acc, wrow, wcol, lr, lc, cg, P, P+128, P+256, RS0, RQ0);
        store_acc16(acc, A, wrow, wcol, lr, lc);
        __syncthreads();

        #pragma unroll
        for (int i = 0; i < 4; ++i) { acc[i][0]=acc[i][1]=acc[i][2]=acc[i][3]=0.f; }
        gemm16x32(sA, sWB, aoff, boff, acc);
        ln16<true, true>(acc, wrow, wcol, lr, lc, cg, P+384, P+512, P+640, RS1, RQ1);

        // scatter-max (predicated: relu zeros are no-ops vs init 0)
        #pragma unroll
        for (int hh = 0; hh < 2; ++hh) {
            int row = wrow + hh*8 + lr;
            int grow = r0 + row; if (grow >= NROWS) grow = NROWS - 1;
            int ln = __ldg(lane_ids + grow);
            int* bp = g_lanemax + ln * HD;
            #pragma unroll
            for (int nt = 0; nt < 4; ++nt) {
                int c = wcol + nt*8 + lc*2;
                float v0 = acc[nt][hh*2+0], v1 = acc[nt][hh*2+1];
                if (v0 > 0.f) atomicMax(bp + c,     __float_as_int(v0));
                if (v1 > 0.f) atomicMax(bp + c + 1, __float_as_int(v1));
            }
        }
        store_acc16(acc, A, wrow, wcol, lr, lc);   // h image (fp16)
        __syncthreads();

        const uint4* s4 = (const uint4*)A;
        uint4* d4 = g_h + (size_t)t * TU64H;
        #pragma unroll
        for (int j = 0; j < 3; ++j) {
            int i = tid + j * 512;
            if (i < TU64H) d4[i] = s4[i];
        }
        __syncthreads();
    }
}

// ======================== k_lanegemm (unchanged from R15; 32x32 warp tile) ========================
static __device__ __forceinline__ void gemm32x32(
    u32 A, u32 B, u32 aoff, u32 boff, float (&acc)[8][4])
{
    #pragma unroll
    for (int kc = 0; kc < 8; ++kc) {
        const u32 ka = kc * 32;
        u32 a0[4], a1[4], b[8];
        ldsm4(a0[0], a0[1], a0[2], a0[3], A + aoff + ka);
        ldsm4(a1[0], a1[1], a1[2], a1[3], A + aoff + 16 * ROWB + ka);
        ldsm4(b[0], b[1], b[2], b[3], B + boff + ka);
        ldsm4(b[4], b[5], b[6], b[7], B + boff + 16 * ROWB + ka);
        #pragma unroll
        for (int p = 0; p < 2; ++p)
        #pragma unroll
        for (int j = 0; j < 2; ++j) {
            const int nt = p * 2 + j;
            const u32 b0 = b[p*4 + j*2], b1 = b[p*4 + j*2 + 1];
            mma_f16(acc[nt],     a0, b0, b1);
            mma_f16(acc[4 + nt], a1, b0, b1);
        }
    }
}

__global__ void __launch_bounds__(512, 1) k_lanegemm(
    const float* __restrict__ w2a_bot, const float* __restrict__ b2a)
{
    extern __shared__ char sm[];
    u32* W = (u32*)(sm);
    u32* A = (u32*)(sm + WSZ);
    float* P = (float*)(sm + 2*WSZ);

    const int tid = threadIdx.x, w = tid >> 5, lane = tid & 31;
    const int lr = lane >> 2, lc = lane & 3;
    const int wrow = (w & 3) * 32, wcol = (w >> 2) * 32;
    const u32 aoff = mk_aoff(wrow, lane), boff = mk_boff(wcol, lane);
    const u32 sA = smem_u32(A), sW = smem_u32(W);

    load_w_f16(W, w2a_bot, tid, 512);
    for (int i = tid; i < HD; i += 512) P[i] = b2a[i];
    __syncthreads();

    for (int t = blockIdx.x; t < NLT; t += gridDim.x) {
        int l0 = t * 128;
        #pragma unroll
        for (int j = 0; j < 8; ++j) {
            int idx = tid + j * 512; int xr = idx >> 5; int cgp = idx & 31;
            int l = l0 + xr; if (l >= NLANES) l = NLANES - 1;
            int4 gv = __ldg(((const int4*)(g_lanemax)) + ((size_t)l * 32 + cgp));
            store4_f16(A, xr, cgp * 4,
                make_float4(__int_as_float(gv.x), __int_as_float(gv.y),
                            __int_as_float(gv.z), __int_as_float(gv.w)));
        }
        __syncthreads();

        float acc[8][4];
        #pragma unroll
        for (int i = 0; i < 8; ++i) { acc[i][0]=acc[i][1]=acc[i][2]=acc[i][3]=0.f; }
        gemm32x32(sA, sW, aoff, boff, acc);

        #pragma unroll
        for (int rt = 0; rt < 2; ++rt)
        #pragma unroll
        for (int hh = 0; hh < 2; ++hh) {
            int row = wrow + rt*16 + hh*8 + lr;
            int l = l0 + row;
            if (l < NLANES) {
                #pragma unroll
                for (int nt = 0; nt < 4; ++nt) {
                    int c = wcol + nt*8 + lc*2;
                    *(float2*)(g_z + (size_t)l * HD + c) =
                        make_float2(acc[rt*4+nt][hh*2+0] + P[c],
                                    acc[rt*4+nt][hh*2+1] + P[c+1]);
                }
            }
        }
        __syncthreads();
    }
}

// ======================== fused fc2 (fp16 1-pass, 16 warps, 2 CTAs/SM, dbl-buffered A) ========================
// smem: WA 0 | WB WSZ | A0 2WSZ | A1 2WSZ+ASZ | P 2WSZ+2ASZ (3584B) | RS/RQ x2
__global__ void __launch_bounds__(512, 2) k_fc2(
    const float* __restrict__ x, const int* __restrict__ lane_ids,
    const float* __restrict__ w2a_top,
    const float* __restrict__ g2a, const float* __restrict__ be2a,
    const float* __restrict__ w2b, const float* __restrict__ b2b,
    const float* __restrict__ g2b, const float* __restrict__ be2b,
    const float* __restrict__ gn, const float* __restrict__ bn,
    float* __restrict__ out)
{
    extern __shared__ char sm[];
    u32* WA = (u32*)(sm);
    u32* WB = (u32*)(sm + WSZ);
    float* P   = (float*)(sm + 2*WSZ + 2*ASZ);
    float* RS0 = (float*)(sm + 2*WSZ + 2*ASZ + 3584);
    float* RQ0 = (float*)(sm + 2*WSZ + 2*ASZ + 4608);
    float* RS1 = (float*)(sm + 2*WSZ + 2*ASZ + 5632);
    float* RQ1 = (float*)(sm + 2*WSZ + 2*ASZ + 6656);

    const int tid = threadIdx.x, w = tid >> 5, lane = tid & 31;
    const int lr = lane >> 2, lc = lane & 3;
    const int wrow = (w & 3) * 16, wcol = (w >> 2) * 32, cg = w >> 2;
    const u32 aoff = mk_aoff(wrow, lane), boff = mk_boff(wcol, lane);
    const u32 sWA = smem_u32(WA), sWB = smem_u32(WB);
    const u32 sA0 = smem_u32(sm + 2*WSZ), sA1 = smem_u32(sm + 2*WSZ + ASZ);

    // prologue: issue first h-image load FIRST (overlaps weight loads)
    {
        const uint4* s4 = g_h + (size_t)blockIdx.x * TU64H;
        #pragma unroll
        for (int j = 0; j < 3; ++j) {
            int i = tid + j * 512;
            if (i < TU64H) CP16(sA0 + (u32)i * 16, s4 + i);
        }
        CP_COMMIT();
    }
    load_w_f16(WA, w2a_top, tid, 512);
    load_w_f16(WB, w2b,     tid, 512);
    for (int i = tid; i < HD; i += 512) {
        P[i]       = g2a[i]; P[128+i] = be2a[i];
        P[256+i]   = b2b[i]; P[384+i] = g2b[i]; P[512+i] = be2b[i];
        P[640+i]   = gn[i];  P[768+i] = bn[i];
    }
    if (tid < 256) {
        int grow = blockIdx.x * TM64 + (tid >> 2);
        if (grow < NROWS) PREF_L2((const char*)x + (size_t)blockIdx.x * TM64 * HD * 4 + tid * 128);
    }
    __syncthreads();

    int buf = 0;
    for (int t = blockIdx.x; t < NT64; t += gridDim.x, buf ^= 1) {
        int r0 = t * TM64;
        int tn = t + gridDim.x; if (tn >= NT64) tn = t;
        const u32 sA  = buf ? sA1 : sA0;
        const u32 sAn = buf ? sA0 : sA1;
        u32* Acur = (u32*)(sm + 2*WSZ + (buf ? ASZ : 0));

        CP_WAIT0();                       // current h image resident
        __syncthreads();

        // issue NEXT tile's h image into the other buffer NOW — overlaps both GEMMs
        {
            const uint4* s4 = g_h + (size_t)tn * TU64H;
            #pragma unroll
            for (int j = 0; j < 3; ++j) {
                int i = tid + j * 512;
                if (i < TU64H) CP16(sAn + (u32)i * 16, s4 + i);
            }
            CP_COMMIT();
            if (tid < 256) {
                int grow = tn * TM64 + (tid >> 2);
                if (grow < NROWS) PREF_L2((const char*)x + (size_t)tn * TM64 * HD * 4 + tid * 128);
            }
        }
        // prefetch this tile's Z rows into L2
        if (tid < 256) {
            int grow = r0 + (tid >> 2); if (grow >= NROWS) grow = NROWS - 1;
            int lnid = __ldg(lane_ids + grow);
            PREF_L2(g_z + (size_t)lnid * HD + (tid & 3) * 32);
        }

        float acc[4][4];
        #pragma unroll
        for (int i = 0; i < 4; ++i) { acc[i][0]=acc[i][1]=acc[i][2]=acc[i][3]=0.f; }
        gemm16x32(sA, sWA, aoff, boff, acc);

        // add Z[lane] (fp32, b2a folded in)
        #pragma unroll
        for (int hh = 0; hh < 2; ++hh) {
            int row = wrow + hh*8 + lr;
            int grow = r0 + row; if (grow >= NROWS) grow = NROWS - 1;
            int lnid = __ldg(lane_ids + grow);
            const float* zr = g_z + (size_t)lnid * HD;
            #pragma unroll
            for (int nt = 0; nt < 4; ++nt) {
                int c = wcol + nt*8 + lc*2;
                float2 zv = __ldg((const float2*)(zr + c));
                acc[nt][hh*2+0] += zv.x;
                acc[nt][hh*2+1] += zv.y;
            }
        }
        // LN1 + ReLU (set0; its barrier also guarantees all GEMM1 A-reads done)
        ln16<false, true>(acc, wrow, wcol, lr, lc, cg, P, P, P+128, RS0, RQ0);

        // store f into current A (in place; safe per LN1 barrier)
        store_acc16(acc, Acur, wrow, wcol, lr, lc);
        __syncthreads();

        // GEMM2: f @ w2b
        #pragma unroll
        for (int i = 0; i < 4; ++i) { acc[i][0]=acc[i][1]=acc[i][2]=acc[i][3]=0.f; }
        gemm16x32(sA, sWB, aoff, boff, acc);

        // LN2 + ReLU (set1; its barrier covers GEMM2 A-reads before next-iter cp into this buffer)
        ln16<true, true>(acc, wrow, wcol, lr, lc, cg, P+256, P+384, P+512, RS1, RQ1);

        // residual add from x (L2-hot)
        #pragma unroll
        for (int hh = 0; hh < 2; ++hh) {
            int row = wrow + hh*8 + lr;
            int grow = r0 + row; if (grow >= NROWS) grow = NROWS - 1;
            #pragma unroll
            for (int nt = 0; nt < 4; ++nt) {
                int c = wcol + nt*8 + lc*2;
                float2 xv = __ldg((const float2*)(x + (size_t)grow * HD + c));
                acc[nt][hh*2+0] += xv.x;
                acc[nt][hh*2+1] += xv.y;
            }
        }
        // final LN (set0 — safe: last set0 read was LN1, separated by f-store barrier)
        ln16<false, false>(acc, wrow, wcol, lr, lc, cg, P, P+640, P+768, RS0, RQ0);

        // write out straight from registers
        #pragma unroll
        for (int hh = 0; hh < 2; ++hh) {
            int row = wrow + hh*8 + lr;
            int grow = r0 + row;
            if (grow < NROWS) {
                #pragma unroll
                for (int nt = 0; nt < 4; ++nt) {
                    int c = wcol + nt*8 + lc*2;
                    *(float2*)(out + (size_t)grow * HD + c) =
                        make_float2(acc[nt][hh*2+0], acc[nt][hh*2+1]);
                }
            }
        }
        // loop-top CP_WAIT0 + __syncthreads gates buffer & RS reuse
    }
}

// ---------------- launcher ----------------
extern "C" void kernel_launch(void* const* d_in, const int* in_sizes, int n_in,
                              void* d_out, int out_size) {
    (void)in_sizes; (void)n_in; (void)out_size;
    const float* x        = (const float*)d_in[0];
    const int*   lane_ids = (const int*)  d_in[1];
    const float* w1a  = (const float*)d_in[2];
    const float* b1a  = (const float*)d_in[3];
    const float* g1a  = (const float*)d_in[4];
    const float* be1a = (const float*)d_in[5];
    const float* w1b  = (const float*)d_in[6];
    const float* b1b  = (const float*)d_in[7];
    const float* g1b  = (const float*)d_in[8];
    const float* be1b = (const float*)d_in[9];
    const float* w2a  = (const float*)d_in[10];
    const float* b2a  = (const float*)d_in[11];
    const float* g2a  = (const float*)d_in[12];
    const float* be2a = (const float*)d_in[13];
    const float* w2b  = (const float*)d_in[14];
    const float* b2b  = (const float*)d_in[15];
    const float* g2b  = (const float*)d_in[16];
    const float* be2b = (const float*)d_in[17];
    const float* gn   = (const float*)d_in[18];
    const float* bn   = (const float*)d_in[19];
    float* out = (float*)d_out;

    const int SM1  = 2*WSZ + ASZ + 3072 + 4096;     // 94208
    const int SMLG = 2*WSZ + 1024;                  // 70656
    const int SM2  = 2*WSZ + 2*ASZ + 3584 + 4096;   // 112128
    cudaFuncSetAttribute(k_fc1,      cudaFuncAttributeMaxDynamicSharedMemorySize, SM1);
    cudaFuncSetAttribute(k_lanegemm, cudaFuncAttributeMaxDynamicSharedMemorySize, SMLG);
    cudaFuncSetAttribute(k_fc2,      cudaFuncAttributeMaxDynamicSharedMemorySize, SM2);

    k_init_lanemax<<<(NLANES * HD + 511) / 512, 512>>>();
    k_fc1     <<<296, 512, SM1>>> (x, lane_ids, w1a, b1a, g1a, be1a, w1b, b1b, g1b, be1b);
    k_lanegemm<<<148, 512, SMLG>>>(w2a + 128 * HD, b2a);
    k_fc2     <<<296, 512, SM2>>> (x, lane_ids, w2a, g2a, be2a, w2b, b2b, g2b, be2b, gn, bn, out);
}

// round 17
// speedup vs baseline: 1.1316x; 1.1316x over previous
#include <cuda_runtime.h>
#include <cuda_fp16.h>
#include <cstdint>

#define NROWS  300000
#define HD     128
#define NLANES 25000
#define LNEPS  1e-5f
#define TM64   64
#define NT64   ((NROWS + TM64 - 1) / TM64)  // 4688 tiles (64-row)
#define NLT    ((NLANES + 127) / 128)       // 196 lane tiles
#define PADU   68                            // u32 per 128-fp16 row (272B, conflict-free)
#define ROWB   272
#define TU64H  1088                          // uint4 per 64-row fp16 tile image

typedef unsigned int       u32;
typedef unsigned short     u16;
typedef unsigned long long u64;

// ---------------- device scratch ----------------
__device__ uint4 g_h[(size_t)NT64 * TU64H];  // fc1 output image (fp16, 64-row tiles)
__device__ int   g_lanemax[NLANES * HD];     // per-lane max (float bits, relu>=0)
__device__ float g_z[(size_t)NLANES * HD];   // per-lane Z = max @ w2a_bot + b2a

// ---------------- helpers ----------------
static __device__ __forceinline__ u32 smem_u32(const void* p) {
    u32 a;
    asm("{ .reg .u64 t; cvta.to.shared.u64 t, %1; cvt.u32.u64 %0, t; }" : "=r"(a) : "l"(p));
    return a;
}
static __device__ __forceinline__ u32 pack_f16(float v0, float v1) {
    __half2 h = __floats2half2_rn(v0, v1);
    return *reinterpret_cast<u32*>(&h);
}

#define CP16(sm_addr, gptr) \
    asm volatile("cp.async.cg.shared.global [%0], [%1], 16;" :: "r"(sm_addr), "l"(gptr))
#define CP_COMMIT() asm volatile("cp.async.commit_group;" ::: "memory")
#define CP_WAIT0()  asm volatile("cp.async.wait_group 0;" ::: "memory")
#define PREF_L2(p)  asm volatile("prefetch.global.L2 [%0];" :: "l"(p))

static __device__ __forceinline__ void ldsm4(u32& r0, u32& r1, u32& r2, u32& r3, u32 addr) {
    asm volatile("ldmatrix.sync.aligned.m8n8.x4.shared.b16 {%0,%1,%2,%3}, [%4];"
        : "=r"(r0), "=r"(r1), "=r"(r2), "=r"(r3) : "r"(addr));
}
static __device__ __forceinline__ void mma_f16(float (&d)[4], const u32 (&a)[4], u32 b0, u32 b1) {
    asm volatile("mma.sync.aligned.m16n8k16.row.col.f32.f16.f16.f32 "
        "{%0,%1,%2,%3}, {%4,%5,%6,%7}, {%8,%9}, {%0,%1,%2,%3};"
        : "+f"(d[0]), "+f"(d[1]), "+f"(d[2]), "+f"(d[3])
        : "r"(a[0]), "r"(a[1]), "r"(a[2]), "r"(a[3]), "r"(b0), "r"(b1));
}

// fp16 single-pass GEMM: acc += A*B over K=128. Warp covers 32x32.
static __device__ __forceinline__ void gemm_f16_1p(
    u32 A, u32 B, u32 aoff, u32 boff, float (&acc)[8][4])
{
    #pragma unroll
    for (int kc = 0; kc < 8; ++kc) {
        const u32 ka = kc * 32;
        u32 a0[4], a1[4], b[8];
        ldsm4(a0[0], a0[1], a0[2], a0[3], A + aoff + ka);
        ldsm4(a1[0], a1[1], a1[2], a1[3], A + aoff + 16 * ROWB + ka);
        ldsm4(b[0], b[1], b[2], b[3], B + boff + ka);
        ldsm4(b[4], b[5], b[6], b[7], B + boff + 16 * ROWB + ka);
        #pragma unroll
        for (int p = 0; p < 2; ++p)
        #pragma unroll
        for (int j = 0; j < 2; ++j) {
            const int nt = p * 2 + j;
            const u32 b0 = b[p*4 + j*2], b1 = b[p*4 + j*2 + 1];
            mma_f16(acc[nt],     a0, b0, b1);
            mma_f16(acc[4 + nt], a1, b0, b1);
        }
    }
}

// ---------------- LN epilogue for 64-row tiles (single barrier; ping-pong RS/RQ) ----------------
template<bool HASB, bool RELU>
static __device__ __forceinline__ void ln_tile64(
    float (&acc)[8][4], int wrow, int wcol, int lr, int lc, int cw,
    const float* __restrict__ bias, const float* __restrict__ gam,
    const float* __restrict__ bet, float* RS, float* RQ)
{
    float s[4] = {0.f,0.f,0.f,0.f}, q[4] = {0.f,0.f,0.f,0.f};
    #pragma unroll
    for (int rt = 0; rt < 2; ++rt)
    #pragma unroll
    for (int nt = 0; nt < 4; ++nt) {
        float* a = acc[rt * 4 + nt];
        if (HASB) {
            int c = wcol + nt * 8 + lc * 2;
            float bx = bias[c], by = bias[c + 1];
            a[0] += bx; a[1] += by; a[2] += bx; a[3] += by;
        }
        s[rt*2+0] += a[0] + a[1]; q[rt*2+0] += a[0]*a[0] + a[1]*a[1];
        s[rt*2+1] += a[2] + a[3]; q[rt*2+1] += a[2]*a[2] + a[3]*a[3];
    }
    #pragma unroll
    for (int off = 1; off <= 2; off <<= 1)
        #pragma unroll
        for (int i = 0; i < 4; ++i) {
            s[i] += __shfl_xor_sync(0xffffffffu, s[i], off);
            q[i] += __shfl_xor_sync(0xffffffffu, q[i], off);
        }
    if (lc == 0) {
        #pragma unroll
        for (int i = 0; i < 4; ++i) {
            int row = wrow + (i >> 1) * 16 + (i & 1) * 8 + lr;
            RS[cw * 64 + row] = s[i];
            RQ[cw * 64 + row] = q[i];
        }
    }
    __syncthreads();
    float mm[4], rsd[4];
    #pragma unroll
    for (int i = 0; i < 4; ++i) {
        int row = wrow + (i >> 1) * 16 + (i & 1) * 8 + lr;
        float S = RS[row] + RS[64 + row] + RS[128 + row] + RS[192 + row];
        float Q = RQ[row] + RQ[64 + row] + RQ[128 + row] + RQ[192 + row];
        float m = S * (1.f / 128.f);
        mm[i] = m;
        rsd[i] = rsqrtf(Q * (1.f / 128.f) - m * m + LNEPS);
    }
    #pragma unroll
    for (int rt = 0; rt < 2; ++rt)
    #pragma unroll
    for (int nt = 0; nt < 4; ++nt) {
        int c = wcol + nt * 8 + lc * 2;
        float gx = gam[c], gy = gam[c + 1], ex = bet[c], ey = bet[c + 1];
        float* a = acc[rt * 4 + nt];
        int s0 = rt * 2, s1 = rt * 2 + 1;
        a[0] = (a[0] - mm[s0]) * rsd[s0] * gx + ex;
        a[1] = (a[1] - mm[s0]) * rsd[s0] * gy + ey;
        a[2] = (a[2] - mm[s1]) * rsd[s1] * gx + ex;
        a[3] = (a[3] - mm[s1]) * rsd[s1] * gy + ey;
        if (RELU) {
            a[0] = fmaxf(a[0], 0.f); a[1] = fmaxf(a[1], 0.f);
            a[2] = fmaxf(a[2], 0.f); a[3] = fmaxf(a[3], 0.f);
        }
    }
}

// fp16 fragment store (hi only)
static __device__ __forceinline__ void store_acc_f16(
    const float (&acc)[8][4], u32* dst, int wrow, int wcol, int lr, int lc)
{
    #pragma unroll
    for (int rt = 0; rt < 2; ++rt)
    #pragma unroll
    for (int hh = 0; hh < 2; ++hh) {
        int row = wrow + rt * 16 + hh * 8 + lr;
        u32 base = row * PADU + (wcol >> 1) + lc;
        #pragma unroll
        for (int nt = 0; nt < 4; ++nt)
            dst[base + nt*4] = pack_f16(acc[rt*4+nt][hh*2+0], acc[rt*4+nt][hh*2+1]);
    }
}

static __device__ __forceinline__ void store4_f16(u32* dst, int row, int col, float4 xv) {
    u32 idx = row * PADU + (col >> 1);
    dst[idx]   = pack_f16(xv.x, xv.y);
    dst[idx+1] = pack_f16(xv.z, xv.w);
}

// single-fp16 weight loader
static __device__ __forceinline__ void load_w_f16(u32* dst, const float* __restrict__ w,
                                                  int tid, int nth) {
    for (int idx = tid; idx < HD * HD / 2; idx += nth) {
        int o = idx & 127, k2 = idx >> 7;
        dst[o * PADU + k2] = pack_f16(w[(2*k2) * HD + o], w[(2*k2+1) * HD + o]);
    }
}

__global__ void k_init_lanemax() {
    int i = blockIdx.x * blockDim.x + threadIdx.x;
    if (i < NLANES * HD) g_lanemax[i] = 0;
}

#define WSZ  34816    // 128x68 u32 (weights / 128-row arrays)
#define ASZ  17408    // 64x68 u32  (64-row activation arrays)

static __device__ __forceinline__ u32 mk_aoff(int wrow, int lane) {
    return (u32)((wrow + (lane & 15)) * ROWB + ((lane >> 4) & 1) * 16);
}
static __device__ __forceinline__ u32 mk_boff(int wcol, int lane) {
    return (u32)((wcol + ((lane >> 4) & 1) * 8 + (lane & 7)) * ROWB + ((lane >> 3) & 1) * 16);
}

// ======================== fc1 (fp16 1-pass, 64-row tiles, 2 CTAs/SM) ========================
// smem: WA 0 | WB WSZ | A 2WSZ | P 2WSZ+ASZ (3072B) | RS/RQ x2 (4x1024)
__global__ void __launch_bounds__(256, 2) k_fc1(
    const float* __restrict__ x, const int* __restrict__ lane_ids,
    const float* __restrict__ w1a, const float* __restrict__ b1a,
    const float* __restrict__ g1a, const float* __restrict__ be1a,
    const float* __restrict__ w1b, const float* __restrict__ b1b,
    const float* __restrict__ g1b, const float* __restrict__ be1b)
{
    extern __shared__ char sm[];
    u32* WA = (u32*)(sm);
    u32* WB = (u32*)(sm + WSZ);
    u32* A  = (u32*)(sm + 2*WSZ);
    float* P   = (float*)(sm + 2*WSZ + ASZ);
    float* RS0 = (float*)(sm + 2*WSZ + ASZ + 3072);
    float* RQ0 = (float*)(sm + 2*WSZ + ASZ + 4096);
    float* RS1 = (float*)(sm + 2*WSZ + ASZ + 5120);
    float* RQ1 = (float*)(sm + 2*WSZ + ASZ + 6144);

    const int tid = threadIdx.x, w = tid >> 5, lane = tid & 31;
    const int lr = lane >> 2, lc = lane & 3;
    const int wrow = (w & 1) * 32, wcol = (w >> 1) * 32, cw = w >> 1;
    const u32 aoff = mk_aoff(wrow, lane), boff = mk_boff(wcol, lane);
    const u32 sA = smem_u32(A), sWA = smem_u32(WA), sWB = smem_u32(WB);

    load_w_f16(WA, w1a, tid, 256);
    load_w_f16(WB, w1b, tid, 256);
    for (int i = tid; i < HD; i += 256) {
        P[i] = b1a[i]; P[128+i] = g1a[i]; P[256+i] = be1a[i];
        P[384+i] = b1b[i]; P[512+i] = g1b[i]; P[640+i] = be1b[i];
    }
    {
        int grow = blockIdx.x * TM64 + (tid >> 2);
        if (grow < NROWS) PREF_L2((const char*)x + (size_t)blockIdx.x * TM64 * HD * 4 + tid * 128);
    }
    __syncthreads();

    for (int t = blockIdx.x; t < NT64; t += gridDim.x) {
        int r0 = t * TM64;
        // load + convert x tile (64 rows x 32 float4 = 2048)
        #pragma unroll
        for (int j = 0; j < 8; ++j) {
            int idx = tid + j * 256; int xr = idx >> 5; int cg = idx & 31;
            int grow = r0 + xr; if (grow >= NROWS) grow = NROWS - 1;
            float4 xv = __ldg(((const float4*)x) + ((size_t)grow * 32 + cg));
            store4_f16(A, xr, cg * 4, xv);
        }
        {
            int tn = t + gridDim.x; if (tn >= NT64) tn = t;
            int grow = tn * TM64 + (tid >> 2);
            if (grow < NROWS) PREF_L2((const char*)x + (size_t)tn * TM64 * HD * 4 + tid * 128);
        }
        __syncthreads();

        float acc[8][4];
        #pragma unroll
        for (int i = 0; i < 8; ++i) { acc[i][0]=acc[i][1]=acc[i][2]=acc[i][3]=0.f; }
        gemm_f16_1p(sA, sWA, aoff, boff, acc);
        ln_tile64<true, true>(acc, wrow, wcol, lr, lc, cw, P, P+128, P+256, RS0, RQ0);
        store_acc_f16(acc, A, wrow, wcol, lr, lc);
        __syncthreads();

        #pragma unroll
        for (int i = 0; i < 8; ++i) { acc[i][0]=acc[i][1]=acc[i][2]=acc[i][3]=0.f; }
        gemm_f16_1p(sA, sWB, aoff, boff, acc);
        ln_tile64<true, true>(acc, wrow, wcol, lr, lc, cw, P+384, P+512, P+640, RS1, RQ1);

        // scatter-max (predicated: relu zeros are no-ops vs init 0)
        #pragma unroll
        for (int rt = 0; rt < 2; ++rt)
        #pragma unroll
        for (int hh = 0; hh < 2; ++hh) {
            int row = wrow + rt*16 + hh*8 + lr;
            int grow = r0 + row; if (grow >= NROWS) grow = NROWS - 1;
            int ln = __ldg(lane_ids + grow);
            int* bp = g_lanemax + ln * HD;
            #pragma unroll
            for (int nt = 0; nt < 4; ++nt) {
                int c = wcol + nt*8 + lc*2;
                float v0 = acc[rt*4+nt][hh*2+0], v1 = acc[rt*4+nt][hh*2+1];
                if (v0 > 0.f) atomicMax(bp + c,     __float_as_int(v0));
                if (v1 > 0.f) atomicMax(bp + c + 1, __float_as_int(v1));
            }
        }
        store_acc_f16(acc, A, wrow, wcol, lr, lc);   // h image (fp16)
        __syncthreads();

        const uint4* s4 = (const uint4*)A;
        uint4* d4 = g_h + (size_t)t * TU64H;
        #pragma unroll
        for (int j = 0; j < 5; ++j) {
            int i = tid + j * 256;
            if (i < TU64H) d4[i] = s4[i];
        }
        __syncthreads();
    }
}

// ======================== k_lanegemm: Z = lane_max @ w2a_bot + b2a (fp16 1-pass, 512 thr) ========================
__global__ void __launch_bounds__(512, 1) k_lanegemm(
    const float* __restrict__ w2a_bot, const float* __restrict__ b2a)
{
    extern __shared__ char sm[];
    u32* W = (u32*)(sm);
    u32* A = (u32*)(sm + WSZ);              // 128-lane tile (WSZ)
    float* P = (float*)(sm + 2*WSZ);        // b2a

    const int tid = threadIdx.x, w = tid >> 5, lane = tid & 31;
    const int lr = lane >> 2, lc = lane & 3;
    const int wrow = (w & 3) * 32, wcol = (w >> 2) * 32;
    const u32 aoff = mk_aoff(wrow, lane), boff = mk_boff(wcol, lane);
    const u32 sA = smem_u32(A), sW = smem_u32(W);

    load_w_f16(W, w2a_bot, tid, 512);
    for (int i = tid; i < HD; i += 512) P[i] = b2a[i];
    __syncthreads();

    for (int t = blockIdx.x; t < NLT; t += gridDim.x) {
        int l0 = t * 128;
        #pragma unroll
        for (int j = 0; j < 8; ++j) {
            int idx = tid + j * 512; int xr = idx >> 5; int cg = idx & 31;
            int l = l0 + xr; if (l >= NLANES) l = NLANES - 1;
            int4 gv = __ldg(((const int4*)(g_lanemax)) + ((size_t)l * 32 + cg));
            store4_f16(A, xr, cg * 4,
                make_float4(__int_as_float(gv.x), __int_as_float(gv.y),
                            __int_as_float(gv.z), __int_as_float(gv.w)));
        }
        __syncthreads();

        float acc[8][4];
        #pragma unroll
        for (int i = 0; i < 8; ++i) { acc[i][0]=acc[i][1]=acc[i][2]=acc[i][3]=0.f; }
        gemm_f16_1p(sA, sW, aoff, boff, acc);

        #pragma unroll
        for (int rt = 0; rt < 2; ++rt)
        #pragma unroll
        for (int hh = 0; hh < 2; ++hh) {
            int row = wrow + rt*16 + hh*8 + lr;
            int l = l0 + row;
            if (l < NLANES) {
                #pragma unroll
                for (int nt = 0; nt < 4; ++nt) {
                    int c = wcol + nt*8 + lc*2;
                    *(float2*)(g_z + (size_t)l * HD + c) =
                        make_float2(acc[rt*4+nt][hh*2+0] + P[c],
                                    acc[rt*4+nt][hh*2+1] + P[c+1]);
                }
            }
        }
        __syncthreads();
    }
}

// ======================== fused fc2 (fp16 1-pass, 64-row tiles, 2 CTAs/SM, dbl-buffered A) ========================
// smem: WA 0 | WB WSZ | A0 2WSZ | A1 2WSZ+ASZ | P 2WSZ+2ASZ (3584B) | RS/RQ x2
__global__ void __launch_bounds__(256, 2) k_fc2(
    const float* __restrict__ x, const int* __restrict__ lane_ids,
    const float* __restrict__ w2a_top,
    const float* __restrict__ g2a, const float* __restrict__ be2a,
    const float* __restrict__ w2b, const float* __restrict__ b2b,
    const float* __restrict__ g2b, const float* __restrict__ be2b,
    const float* __restrict__ gn, const float* __restrict__ bn,
    float* __restrict__ out)
{
    extern __shared__ char sm[];
    u32* WA = (u32*)(sm);
    u32* WB = (u32*)(sm + WSZ);
    float* P   = (float*)(sm + 2*WSZ + 2*ASZ);
    float* RS0 = (float*)(sm + 2*WSZ + 2*ASZ + 3584);
    float* RQ0 = (float*)(sm + 2*WSZ + 2*ASZ + 4608);
    float* RS1 = (float*)(sm + 2*WSZ + 2*ASZ + 5632);
    float* RQ1 = (float*)(sm + 2*WSZ + 2*ASZ + 6656);

    const int tid = threadIdx.x, w = tid >> 5, lane = tid & 31;
    const int lr = lane >> 2, lc = lane & 3;
    const int wrow = (w & 1) * 32, wcol = (w >> 1) * 32, cw = w >> 1;
    const u32 aoff = mk_aoff(wrow, lane), boff = mk_boff(wcol, lane);
    const u32 sWA = smem_u32(WA), sWB = smem_u32(WB);
    const u32 sA0 = smem_u32(sm + 2*WSZ), sA1 = smem_u32(sm + 2*WSZ + ASZ);

    // prologue: issue first h-image load FIRST (overlaps weight loads)
    {
        const uint4* s4 = g_h + (size_t)blockIdx.x * TU64H;
        #pragma unroll
        for (int j = 0; j < 5; ++j) {
            int i = tid + j * 256;
            if (i < TU64H) CP16(sA0 + (u32)i * 16, s4 + i);
        }
        CP_COMMIT();
    }
    load_w_f16(WA, w2a_top, tid, 256);
    load_w_f16(WB, w2b,     tid, 256);
    for (int i = tid; i < HD; i += 256) {
        P[i]       = g2a[i]; P[128+i] = be2a[i];
        P[256+i]   = b2b[i]; P[384+i] = g2b[i]; P[512+i] = be2b[i];
        P[640+i]   = gn[i];  P[768+i] = bn[i];
    }
    {
        int grow = blockIdx.x * TM64 + (tid >> 2);
        if (grow < NROWS) PREF_L2((const char*)x + (size_t)blockIdx.x * TM64 * HD * 4 + tid * 128);
    }
    __syncthreads();

    int buf = 0;
    for (int t = blockIdx.x; t < NT64; t += gridDim.x, buf ^= 1) {
        int r0 = t * TM64;
        int tn = t + gridDim.x; if (tn >= NT64) tn = t;
        const u32 sA  = buf ? sA1 : sA0;
        const u32 sAn = buf ? sA0 : sA1;
        u32* Acur = (u32*)(sm + 2*WSZ + (buf ? ASZ : 0));

        CP_WAIT0();                       // current h image resident
        __syncthreads();

        // issue NEXT tile's h image into the other buffer NOW — overlaps both GEMMs
        {
            const uint4* s4 = g_h + (size_t)tn * TU64H;
            #pragma unroll
            for (int j = 0; j < 5; ++j) {
                int i = tid + j * 256;
                if (i < TU64H) CP16(sAn + (u32)i * 16, s4 + i);
            }
            CP_COMMIT();
            int grow = tn * TM64 + (tid >> 2);
            if (grow < NROWS) PREF_L2((const char*)x + (size_t)tn * TM64 * HD * 4 + tid * 128);
        }
        // prefetch this tile's Z rows into L2
        {
            int grow = r0 + (tid >> 2); if (grow >= NROWS) grow = NROWS - 1;
            int lnid = __ldg(lane_ids + grow);
            PREF_L2(g_z + (size_t)lnid * HD + (tid & 3) * 32);
        }

        float acc[8][4];
        #pragma unroll
        for (int i = 0; i < 8; ++i) { acc[i][0]=acc[i][1]=acc[i][2]=acc[i][3]=0.f; }
        gemm_f16_1p(sA, sWA, aoff, boff, acc);

        // add Z[lane] (fp32, b2a folded in)
        #pragma unroll
        for (int rt = 0; rt < 2; ++rt)
        #pragma unroll
        for (int hh = 0; hh < 2; ++hh) {
            int row = wrow + rt*16 + hh*8 + lr;
            int grow = r0 + row; if (grow >= NROWS) grow = NROWS - 1;
            int lnid = __ldg(lane_ids + grow);
            const float* zr = g_z + (size_t)lnid * HD;
            #pragma unroll
            for (int nt = 0; nt < 4; ++nt) {
                int c = wcol + nt*8 + lc*2;
                float2 zv = __ldg((const float2*)(zr + c));
                acc[rt*4+nt][hh*2+0] += zv.x;
                acc[rt*4+nt][hh*2+1] += zv.y;
            }
        }
        // LN1 + ReLU (set0; its barrier also guarantees all GEMM1 A-reads done)
        ln_tile64<false, true>(acc, wrow, wcol, lr, lc, cw, P, P, P+128, RS0, RQ0);

        // store f into current A (in place; safe per LN1 barrier)
        store_acc_f16(acc, Acur, wrow, wcol, lr, lc);
        __syncthreads();

        // GEMM2: f @ w2b
        #pragma unroll
        for (int i = 0; i < 8; ++i) { acc[i][0]=acc[i][1]=acc[i][2]=acc[i][3]=0.f; }
        gemm_f16_1p(sA, sWB, aoff, boff, acc);

        // LN2 + ReLU (set1; its barrier covers GEMM2 A-reads before next-iter cp into this buffer)
        ln_tile64<true, true>(acc, wrow, wcol, lr, lc, cw, P+256, P+384, P+512, RS1, RQ1);

        // residual add from x (L2-hot)
        #pragma unroll
        for (int rt = 0; rt < 2; ++rt)
        #pragma unroll
        for (int hh = 0; hh < 2; ++hh) {
            int row = wrow + rt*16 + hh*8 + lr;
            int grow = r0 + row; if (grow >= NROWS) grow = NROWS - 1;
            #pragma unroll
            for (int nt = 0; nt < 4; ++nt) {
                int c = wcol + nt*8 + lc*2;
                float2 xv = __ldg((const float2*)(x + (size_t)grow * HD + c));
                acc[rt*4+nt][hh*2+0] += xv.x;
                acc[rt*4+nt][hh*2+1] += xv.y;
            }
        }
        // final LN (set0 — safe: last set0 read was LN1, separated by f-store barrier)
        ln_tile64<false, false>(acc, wrow, wcol, lr, lc, cw, P, P+640, P+768, RS0, RQ0);

        // write out straight from registers
        #pragma unroll
        for (int rt = 0; rt < 2; ++rt)
        #pragma unroll
        for (int hh = 0; hh < 2; ++hh) {
            int row = wrow + rt*16 + hh*8 + lr;
            int grow = r0 + row;
            if (grow < NROWS) {
                #pragma unroll
                for (int nt = 0; nt < 4; ++nt) {
                    int c = wcol + nt*8 + lc*2;
                    *(float2*)(out + (size_t)grow * HD + c) =
                        make_float2(acc[rt*4+nt][hh*2+0], acc[rt*4+nt][hh*2+1]);
                }
            }
        }
        // loop-top CP_WAIT0 + __syncthreads gates buffer & RS reuse
    }
}

// ---------------- launcher ----------------
extern "C" void kernel_launch(void* const* d_in, const int* in_sizes, int n_in,
                              void* d_out, int out_size) {
    (void)in_sizes; (void)n_in; (void)out_size;
    const float* x        = (const float*)d_in[0];
    const int*   lane_ids = (const int*)  d_in[1];
    const float* w1a  = (const float*)d_in[2];
    const float* b1a  = (const float*)d_in[3];
    const float* g1a  = (const float*)d_in[4];
    const float* be1a = (const float*)d_in[5];
    const float* w1b  = (const float*)d_in[6];
    const float* b1b  = (const float*)d_in[7];
    const float* g1b  = (const float*)d_in[8];
    const float* be1b = (const float*)d_in[9];
    const float* w2a  = (const float*)d_in[10];
    const float* b2a  = (const float*)d_in[11];
    const float* g2a  = (const float*)d_in[12];
    const float* be2a = (const float*)d_in[13];
    const float* w2b  = (const float*)d_in[14];
    const float* b2b  = (const float*)d_in[15];
    const float* g2b  = (const float*)d_in[16];
    const float* be2b = (const float*)d_in[17];
    const float* gn   = (const float*)d_in[18];
    const float* bn   = (const float*)d_in[19];
    float* out = (float*)d_out;

    const int SM1  = 2*WSZ + ASZ + 3072 + 4096;     // 94208
    const int SMLG = 2*WSZ + 1024;                  // 70656
    const int SM2  = 2*WSZ + 2*ASZ + 3584 + 4096;   // 112128
    cudaFuncSetAttribute(k_fc1,      cudaFuncAttributeMaxDynamicSharedMemorySize, SM1);
    cudaFuncSetAttribute(k_lanegemm, cudaFuncAttributeMaxDynamicSharedMemorySize, SMLG);
    cudaFuncSetAttribute(k_fc2,      cudaFuncAttributeMaxDynamicSharedMemorySize, SM2);

    k_init_lanemax<<<(NLANES * HD + 511) / 512, 512>>>();
    k_fc1     <<<296, 256, SM1>>> (x, lane_ids, w1a, b1a, g1a, be1a, w1b, b1b, g1b, be1b);
    k_lanegemm<<<148, 512, SMLG>>>(w2a + 128 * HD, b2a);
    k_fc2     <<<296, 256, SM2>>> (x, lane_ids, w2a, g2a, be2a, w2b, b2b, g2b, be2b, gn, bn, out);
}